// round 4
// baseline (speedup 1.0000x reference)
#include <cuda_runtime.h>
#include <cuda_bf16.h>
#include <cstdint>

#define L_SEQ 2048
#define DE    2048
#define DMLP  8192
#define NH    16
#define DA    128

// narrow kernel (128x128 tile)
#define BM 128
#define BN 128
#define BK 64
#define STAGE_BYTES (BM*128 + BN*128)
#define GEMM_SMEM   (3*STAGE_BYTES)

// wide kernel (128x256 tile, 64x64 warp tiles)
#define WBM 128
#define WBN 256
#define WSTAGE (WBM*128 + WBN*128)     // 49152
#define WSMEM  (3*WSTAGE)              // 147456

// ---------------- static device scratch (allocation-free) ----------------
static __device__ __align__(256) __nv_bfloat16 g_xn1 [(size_t)L_SEQ*DE];
static __device__ __align__(256) __nv_bfloat16 g_xn2 [(size_t)L_SEQ*DE];
static __device__ __align__(256) float         g_xn2f[(size_t)L_SEQ*DE];
static __device__ __align__(256) float         g_x2  [(size_t)L_SEQ*DE];
static __device__ __align__(256) __nv_bfloat16 g_Wqt [(size_t)NH*DA*DE];
static __device__ __align__(256) __nv_bfloat16 g_Wkt [(size_t)NH*DA*DE];
static __device__ __align__(256) __nv_bfloat16 g_Wv15t[(size_t)DA*DE];
static __device__ __align__(256) float         g_Wv0 [(size_t)15*DE];
static __device__ __align__(256) float         g_v0  [(size_t)15*L_SEQ];
static __device__ __align__(256) __nv_bfloat16 g_q   [(size_t)NH*L_SEQ*DA];
static __device__ __align__(256) __nv_bfloat16 g_k   [(size_t)NH*L_SEQ*DA];
static __device__ __align__(256) __nv_bfloat16 g_v15 [(size_t)L_SEQ*DA];
static __device__ __align__(256) __nv_bfloat16 g_v15t[(size_t)DA*L_SEQ];
static __device__ __align__(256) __nv_bfloat16 g_E15 [(size_t)L_SEQ*L_SEQ];
static __device__ __align__(256) float         g_den [(size_t)NH*L_SEQ];
static __device__ __align__(256) float         g_num [(size_t)15*L_SEQ];
static __device__ __align__(256) float         g_a15 [(size_t)L_SEQ*DA];
static __device__ __align__(256) __nv_bfloat16 g_yc  [(size_t)L_SEQ*256];
static __device__ __align__(256) __nv_bfloat16 g_Wot [(size_t)DE*256];
static __device__ __align__(256) __nv_bfloat16 g_W1t [(size_t)DMLP*DE];
static __device__ __align__(256) __nv_bfloat16 g_W2t [(size_t)DE*DMLP];
static __device__ __align__(256) __nv_bfloat16 g_h1  [(size_t)L_SEQ*DMLP];

// ---------------- helpers ----------------
__device__ __forceinline__ void cpasync16(uint32_t dst, const void* src) {
    asm volatile("cp.async.cg.shared.global [%0], [%1], 16;\n" :: "r"(dst), "l"(src));
}
__device__ __forceinline__ void cpcommit() { asm volatile("cp.async.commit_group;\n"); }
template<int N> __device__ __forceinline__ void cpwait() {
    asm volatile("cp.async.wait_group %0;\n" :: "n"(N));
}
__device__ __forceinline__ void ldsm4(uint32_t* r, uint32_t addr) {
    asm volatile("ldmatrix.sync.aligned.m8n8.x4.shared.b16 {%0,%1,%2,%3}, [%4];\n"
                 : "=r"(r[0]), "=r"(r[1]), "=r"(r[2]), "=r"(r[3]) : "r"(addr));
}
__device__ __forceinline__ void mma16816(float* c, const uint32_t* a, uint32_t b0, uint32_t b1) {
    asm volatile("mma.sync.aligned.m16n8k16.row.col.f32.bf16.bf16.f32 "
                 "{%0,%1,%2,%3}, {%4,%5,%6,%7}, {%8,%9}, {%0,%1,%2,%3};\n"
                 : "+f"(c[0]), "+f"(c[1]), "+f"(c[2]), "+f"(c[3])
                 : "r"(a[0]), "r"(a[1]), "r"(a[2]), "r"(a[3]), "r"(b0), "r"(b1));
}
__device__ __forceinline__ float fast_exp(float t) {
    if (fabsf(t) < 0.25f) return 1.f + t * (1.f + t * (0.5f + t * 0.16666667f));
    return expf(t);
}
__device__ __forceinline__ float gelu_tanh(float u) {
    float u2 = u * u;
    float w  = 0.7978845608028654f * u * (1.f + 0.044715f * u2);
    float t;
    if (fabsf(w) < 0.5f) {
        float w2 = w * w;
        t = w * (1.f - w2 * (0.33333333f - w2 * (0.13333333f - w2 * 0.05396825f)));
    } else {
        t = tanhf(w);
    }
    return 0.5f * u * (1.f + t);
}

// Epilogues (shared numbering across both kernels):
// 0: bf16 C = acc + bias[n]
// 1: bf16 C = exp(acc*scale); atomicAdd rowsum into den[gm]
// 3: f32  C = 2*aux1 + acc + bias[n]
// 4: bf16 C = gelu(acc + bias[n])
// 5: f32  C = acc + bias[n] + aux1 + aux2
// 6: no store; rowsum/v0-dot atomics into den[z*L+gm], num[z*L+gm]
// 7: atomicAdd f32 C += acc  (split-K)
// 8: bf16 head-pair split store: head = 2z + (gn>>7), col = gn&127
struct GP {
    const __nv_bfloat16* A; int lda; long sA;
    const __nv_bfloat16* B; int ldb; long sB;
    int K;
    const float* bias; int sBias;
    void* C; int ldc; long sC;
    const float* aux1;
    const float* aux2;
    float* den;
    float* num;
    const float* v0;
    float scale;
};

// ---------------- narrow GEMM: 128x128 tile, 32x64 warp tile ----------------
template<int EPI>
__global__ void __launch_bounds__(256) gemm_bf16(GP p) {
    extern __shared__ __align__(128) char smem[];
    const int tid = threadIdx.x;
    const int bm = blockIdx.x * BM;
    const int bn = blockIdx.y * BN;
    const int z  = blockIdx.z;

    const __nv_bfloat16* Ag = p.A + (long)z * p.sA;
    const __nv_bfloat16* Bg = p.B + (long)z * p.sB;

    uint32_t sbase = (uint32_t)__cvta_generic_to_shared(smem);
    const int lr = tid >> 3, lc = tid & 7;
    const __nv_bfloat16* Agp = Ag + (long)(bm + lr) * p.lda + lc * 8;
    const __nv_bfloat16* Bgp = Bg + (long)(bn + lr) * p.ldb + lc * 8;

    float c[2][8][4];
    #pragma unroll
    for (int i = 0; i < 2; i++)
        #pragma unroll
        for (int j = 0; j < 8; j++)
            #pragma unroll
            for (int r = 0; r < 4; r++) c[i][j][r] = 0.f;

    const int KT = p.K / BK;

    auto issue = [&](int kt, int s) {
        uint32_t aS = sbase + s * STAGE_BYTES;
        uint32_t bS = aS + BM * 128;
        const __nv_bfloat16* Ak = Agp + kt * BK;
        const __nv_bfloat16* Bk = Bgp + kt * BK;
        #pragma unroll
        for (int i = 0; i < 4; i++) {
            int r = lr + 32 * i;
            cpasync16(aS + r * 128 + ((lc * 16) ^ ((r & 7) * 16)), Ak + (long)(32 * i) * p.lda);
        }
        #pragma unroll
        for (int i = 0; i < 4; i++) {
            int r = lr + 32 * i;
            cpasync16(bS + r * 128 + ((lc * 16) ^ ((r & 7) * 16)), Bk + (long)(32 * i) * p.ldb);
        }
        cpcommit();
    };

    issue(0, 0);
    if (KT > 1) issue(1, 1);

    const int lane = tid & 31, warp = tid >> 5;
    const int wm = warp & 3, wn = warp >> 2;

    for (int kt = 0; kt < KT; kt++) {
        if (kt < KT - 1) cpwait<1>(); else cpwait<0>();
        __syncthreads();
        if (kt + 2 < KT) issue(kt + 2, (kt + 2) % 3);

        uint32_t aS = sbase + (kt % 3) * STAGE_BYTES;
        uint32_t bS = aS + BM * 128;
        #pragma unroll
        for (int ks = 0; ks < 4; ks++) {
            uint32_t a[2][4];
            #pragma unroll
            for (int i = 0; i < 2; i++) {
                int r  = wm * 32 + i * 16 + (lane & 15);
                int cb = ks * 32 + ((lane >> 4) << 4);
                ldsm4(a[i], aS + r * 128 + (cb ^ ((r & 7) << 4)));
            }
            #pragma unroll
            for (int j4 = 0; j4 < 4; j4++) {
                uint32_t b[4];
                int n  = wn * 64 + j4 * 16 + ((lane >> 4) << 3) + (lane & 7);
                int cb = ks * 32 + (((lane >> 3) & 1) << 4);
                ldsm4(b, bS + n * 128 + (cb ^ ((n & 7) << 4)));
                #pragma unroll
                for (int i = 0; i < 2; i++) {
                    mma16816(c[i][2 * j4],     a[i], b[0], b[1]);
                    mma16816(c[i][2 * j4 + 1], a[i], b[2], b[3]);
                }
            }
        }
    }

    const int row0 = lane >> 2, col0 = (lane & 3) * 2;
    #pragma unroll
    for (int i = 0; i < 2; i++)
        #pragma unroll
        for (int j = 0; j < 8; j++)
            #pragma unroll
            for (int h2 = 0; h2 < 2; h2++) {
                long gm = bm + wm * 32 + i * 16 + h2 * 8 + row0;
                long gn = bn + wn * 64 + j * 8 + col0;
                float a0 = c[i][j][h2 * 2 + 0];
                float a1 = c[i][j][h2 * 2 + 1];
                if (EPI == 0) {
                    __nv_bfloat16* C = (__nv_bfloat16*)p.C + (long)z * p.sC;
                    float x0 = a0 + p.bias[gn], x1 = a1 + p.bias[gn + 1];
                    __nv_bfloat162 pk;
                    pk.x = __float2bfloat16(x0); pk.y = __float2bfloat16(x1);
                    *reinterpret_cast<__nv_bfloat162*>(&C[gm * p.ldc + gn]) = pk;
                } else if (EPI == 7) {
                    float* C = (float*)p.C;
                    long i0 = gm * p.ldc + gn;
                    atomicAdd(&C[i0],     a0);
                    atomicAdd(&C[i0 + 1], a1);
                }
            }
}

// ---------------- wide GEMM: 128x256 tile, 64x64 warp tiles ----------------
template<int EPI>
__global__ void __launch_bounds__(256, 1) gemm_wide(GP p) {
    extern __shared__ __align__(128) char smem[];
    const int tid = threadIdx.x;
    const int bm = blockIdx.x * WBM;
    const int bn = blockIdx.y * WBN;
    const int z  = blockIdx.z;

    const __nv_bfloat16* Ag = p.A + (long)z * p.sA;
    const __nv_bfloat16* Bg = p.B + (long)z * p.sB;

    uint32_t sbase = (uint32_t)__cvta_generic_to_shared(smem);
    const int lr = tid >> 3, lc = tid & 7;
    const __nv_bfloat16* Agp = Ag + (long)(bm + lr) * p.lda + lc * 8;
    const __nv_bfloat16* Bgp = Bg + (long)(bn + lr) * p.ldb + lc * 8;

    float c[4][8][4];
    #pragma unroll
    for (int i = 0; i < 4; i++)
        #pragma unroll
        for (int j = 0; j < 8; j++)
            #pragma unroll
            for (int r = 0; r < 4; r++) c[i][j][r] = 0.f;

    const int KT = p.K / BK;

    auto issue = [&](int kt, int s) {
        uint32_t aS = sbase + s * WSTAGE;
        uint32_t bS = aS + WBM * 128;
        const __nv_bfloat16* Ak = Agp + kt * BK;
        const __nv_bfloat16* Bk = Bgp + kt * BK;
        #pragma unroll
        for (int i = 0; i < 4; i++) {
            int r = lr + 32 * i;
            cpasync16(aS + r * 128 + ((lc * 16) ^ ((r & 7) * 16)), Ak + (long)(32 * i) * p.lda);
        }
        #pragma unroll
        for (int i = 0; i < 8; i++) {
            int r = lr + 32 * i;
            cpasync16(bS + r * 128 + ((lc * 16) ^ ((r & 7) * 16)), Bk + (long)(32 * i) * p.ldb);
        }
        cpcommit();
    };

    issue(0, 0);
    if (KT > 1) issue(1, 1);

    const int lane = tid & 31, warp = tid >> 5;
    const int wm = warp & 1, wn = warp >> 1;   // 2 x 4

    for (int kt = 0; kt < KT; kt++) {
        if (kt < KT - 1) cpwait<1>(); else cpwait<0>();
        __syncthreads();
        if (kt + 2 < KT) issue(kt + 2, (kt + 2) % 3);

        uint32_t aS = sbase + (kt % 3) * WSTAGE;
        uint32_t bS = aS + WBM * 128;
        #pragma unroll
        for (int ks = 0; ks < 4; ks++) {
            uint32_t a[4][4];
            #pragma unroll
            for (int i = 0; i < 4; i++) {
                int r  = wm * 64 + i * 16 + (lane & 15);
                int cb = ks * 32 + ((lane >> 4) << 4);
                ldsm4(a[i], aS + r * 128 + (cb ^ ((r & 7) << 4)));
            }
            #pragma unroll
            for (int j4 = 0; j4 < 4; j4++) {
                uint32_t b[4];
                int n  = wn * 64 + j4 * 16 + ((lane >> 4) << 3) + (lane & 7);
                int cb = ks * 32 + (((lane >> 3) & 1) << 4);
                ldsm4(b, bS + n * 128 + (cb ^ ((n & 7) << 4)));
                #pragma unroll
                for (int i = 0; i < 4; i++) {
                    mma16816(c[i][2 * j4],     a[i], b[0], b[1]);
                    mma16816(c[i][2 * j4 + 1], a[i], b[2], b[3]);
                }
            }
        }
    }

    const int row0 = lane >> 2, col0 = (lane & 3) * 2;

    if (EPI == 1 || EPI == 6) {
        const float* vv = (EPI == 6) ? (p.v0 + (long)z * L_SEQ) : nullptr;
        __nv_bfloat16* C = (__nv_bfloat16*)p.C;
        #pragma unroll
        for (int i = 0; i < 4; i++)
            #pragma unroll
            for (int h2 = 0; h2 < 2; h2++) {
                long gm = bm + wm * 64 + i * 16 + h2 * 8 + row0;
                float se = 0.f, sn = 0.f;
                #pragma unroll
                for (int j = 0; j < 8; j++) {
                    long gn = bn + wn * 64 + j * 8 + col0;
                    float e0 = fast_exp(c[i][j][h2 * 2 + 0] * p.scale);
                    float e1 = fast_exp(c[i][j][h2 * 2 + 1] * p.scale);
                    se += e0 + e1;
                    if (EPI == 6) sn += e0 * vv[gn] + e1 * vv[gn + 1];
                    if (EPI == 1) {
                        __nv_bfloat162 pk;
                        pk.x = __float2bfloat16(e0); pk.y = __float2bfloat16(e1);
                        *reinterpret_cast<__nv_bfloat162*>(&C[gm * p.ldc + gn]) = pk;
                    }
                }
                se += __shfl_xor_sync(0xffffffffu, se, 1);
                se += __shfl_xor_sync(0xffffffffu, se, 2);
                if (EPI == 6) {
                    sn += __shfl_xor_sync(0xffffffffu, sn, 1);
                    sn += __shfl_xor_sync(0xffffffffu, sn, 2);
                }
                if ((lane & 3) == 0) {
                    if (EPI == 1) atomicAdd(&p.den[gm], se);
                    else {
                        atomicAdd(&p.den[(long)z * L_SEQ + gm], se);
                        atomicAdd(&p.num[(long)z * L_SEQ + gm], sn);
                    }
                }
            }
        return;
    }

    #pragma unroll
    for (int i = 0; i < 4; i++)
        #pragma unroll
        for (int j = 0; j < 8; j++)
            #pragma unroll
            for (int h2 = 0; h2 < 2; h2++) {
                long gm = bm + wm * 64 + i * 16 + h2 * 8 + row0;
                long gn = bn + wn * 64 + j * 8 + col0;
                float a0 = c[i][j][h2 * 2 + 0];
                float a1 = c[i][j][h2 * 2 + 1];
                if (EPI == 3) {
                    float* C = (float*)p.C;
                    long i0 = gm * p.ldc + gn;
                    C[i0]     = 2.f * p.aux1[i0]     + a0 + p.bias[gn];
                    C[i0 + 1] = 2.f * p.aux1[i0 + 1] + a1 + p.bias[gn + 1];
                } else if (EPI == 4) {
                    __nv_bfloat16* C = (__nv_bfloat16*)p.C;
                    float x0 = gelu_tanh(a0 + p.bias[gn]);
                    float x1 = gelu_tanh(a1 + p.bias[gn + 1]);
                    __nv_bfloat162 pk;
                    pk.x = __float2bfloat16(x0); pk.y = __float2bfloat16(x1);
                    *reinterpret_cast<__nv_bfloat162*>(&C[gm * p.ldc + gn]) = pk;
                } else if (EPI == 5) {
                    float* C = (float*)p.C;
                    long i0 = gm * p.ldc + gn;
                    C[i0]     = a0 + p.bias[gn]     + p.aux1[i0]     + p.aux2[i0];
                    C[i0 + 1] = a1 + p.bias[gn + 1] + p.aux1[i0 + 1] + p.aux2[i0 + 1];
                } else if (EPI == 8) {
                    int head = z * 2 + (int)(gn >> 7);
                    int col  = (int)(gn & 127);
                    __nv_bfloat16* C = (__nv_bfloat16*)p.C + (long)head * p.sC;
                    float x0 = a0 + p.bias[head * DA + col];
                    float x1 = a1 + p.bias[head * DA + col + 1];
                    __nv_bfloat162 pk;
                    pk.x = __float2bfloat16(x0); pk.y = __float2bfloat16(x1);
                    *reinterpret_cast<__nv_bfloat162*>(&C[gm * DA + col]) = pk;
                }
            }
}

// ---------------- layernorm ----------------
__global__ void ln_kernel(const float* __restrict__ x, const float* __restrict__ g,
                          const float* __restrict__ b, __nv_bfloat16* ob, float* of) {
    int l = blockIdx.x, tid = threadIdx.x;
    const float* row = x + (long)l * DE;
    float v[8], s = 0.f, s2 = 0.f;
    #pragma unroll
    for (int j = 0; j < 8; j++) {
        v[j] = row[tid + 256 * j];
        s += v[j]; s2 += v[j] * v[j];
    }
    __shared__ float sm[18];
    #pragma unroll
    for (int o = 16; o; o >>= 1) {
        s  += __shfl_xor_sync(0xffffffffu, s,  o);
        s2 += __shfl_xor_sync(0xffffffffu, s2, o);
    }
    if ((tid & 31) == 0) { sm[tid >> 5] = s; sm[(tid >> 5) + 8] = s2; }
    __syncthreads();
    if (tid == 0) {
        float a = 0.f, q = 0.f;
        #pragma unroll
        for (int i = 0; i < 8; i++) { a += sm[i]; q += sm[i + 8]; }
        float mean = a / DE;
        float var  = q / DE - mean * mean;
        float sd   = sqrtf(fmaxf(var, 0.f));
        if (sd == 0.f) sd = 1.f;
        sm[16] = mean; sm[17] = 1.f / sd;
    }
    __syncthreads();
    float mean = sm[16], rs = sm[17];
    #pragma unroll
    for (int j = 0; j < 8; j++) {
        int col = tid + 256 * j;
        float y = g[col] * ((v[j] - mean) * rs) + b[col];
        ob[(long)l * DE + col] = __float2bfloat16(y);
        if (of) of[(long)l * DE + col] = y;
    }
}

// ---------------- v0 matvecs, tiled: 16 rows per block ----------------
__global__ void v0_kernel(const __nv_bfloat16* __restrict__ xn1, const float* __restrict__ Wv0,
                          const float* __restrict__ bv, float* __restrict__ v0) {
    extern __shared__ __nv_bfloat16 xr[];   // [16][2048]
    int l0 = blockIdx.x * 16, tid = threadIdx.x;
    // vectorized load: 16*2048 bf16 = 4096 uint4
    const uint4* src = reinterpret_cast<const uint4*>(xn1 + (long)l0 * DE);
    uint4* dst = reinterpret_cast<uint4*>(xr);
    for (int i = tid; i < 16 * DE / 8; i += 256) dst[i] = src[i];
    __syncthreads();
    int lane = tid & 31, warp = tid >> 5;
    for (int task = warp; task < 15 * 16; task += 8) {
        int h = task / 16, l = task % 16;
        const float* w = Wv0 + (long)h * DE;
        const __nv_bfloat16* xrow = xr + (long)l * DE;
        float acc = 0.f;
        for (int k2 = lane; k2 < DE / 2; k2 += 32) {
            float2 xv = __bfloat1622float2(
                *reinterpret_cast<const __nv_bfloat162*>(xrow + 2 * k2));
            acc += xv.x * w[2 * k2] + xv.y * w[2 * k2 + 1];
        }
        #pragma unroll
        for (int o = 16; o; o >>= 1) acc += __shfl_xor_sync(0xffffffffu, acc, o);
        if (lane == 0) v0[(long)h * L_SEQ + l0 + l] = acc + bv[h * DA];
    }
}

// ---------------- weight prep: vectorized fp32->bf16 transpose ----------------
__global__ void transpose_cvt(const float* __restrict__ src, __nv_bfloat16* __restrict__ dst,
                              int R, int C, long sS, long sD) {
    __shared__ float t[32][65];
    src += (long)blockIdx.z * sS;
    dst += (long)blockIdx.z * sD;
    int c0 = blockIdx.x * 32, r0 = blockIdx.y * 64;
    int tid = threadIdx.x;
    #pragma unroll
    for (int j = 0; j < 2; j++) {
        int idx = tid + 256 * j;
        int r   = idx >> 3;
        int c4  = idx & 7;
        float4 v = *reinterpret_cast<const float4*>(src + (long)(r0 + r) * C + c0 + c4 * 4);
        t[c4 * 4 + 0][r] = v.x; t[c4 * 4 + 1][r] = v.y;
        t[c4 * 4 + 2][r] = v.z; t[c4 * 4 + 3][r] = v.w;
    }
    __syncthreads();
    #pragma unroll
    for (int j = 0; j < 4; j++) {
        int idx = tid + 256 * j;
        int c   = idx >> 5;
        int rp  = idx & 31;
        __nv_bfloat162 pk;
        pk.x = __float2bfloat16(t[c][2 * rp]);
        pk.y = __float2bfloat16(t[c][2 * rp + 1]);
        *reinterpret_cast<__nv_bfloat162*>(dst + (long)(c0 + c) * R + r0 + 2 * rp) = pk;
    }
}

__global__ void wo_prep(const float* __restrict__ Wo, __nv_bfloat16* __restrict__ Wot) {
    long idx = (long)blockIdx.x * 256 + threadIdx.x;
    int k = (int)(idx >> 11), n = (int)(idx & 2047);
    float v = (k < 143) ? Wo[(long)k * DE + n] : 0.f;
    Wot[(long)n * 256 + k] = __float2bfloat16(v);
}

__global__ void wv0_prep(const float* __restrict__ Wv, float* __restrict__ Wv0) {
    long idx = (long)blockIdx.x * 256 + threadIdx.x;
    if (idx < 15 * DE) {
        long h = idx / DE, k = idx % DE;
        Wv0[idx] = Wv[(h * DE + k) * DA];
    }
}

__global__ void t_v15(const __nv_bfloat16* __restrict__ src, __nv_bfloat16* __restrict__ dst) {
    __shared__ __nv_bfloat16 t[32][34];
    int c0 = blockIdx.x * 32;
    int r0 = blockIdx.y * 32;
    int tid = threadIdx.x;
    #pragma unroll
    for (int j = 0; j < 2; j++) {
        int idx = tid + 256 * j;
        int r  = idx >> 4;
        int c2 = idx & 15;
        __nv_bfloat162 v = *reinterpret_cast<const __nv_bfloat162*>(
            src + (long)(r0 + r) * DA + c0 + 2 * c2);
        t[2 * c2][r] = v.x; t[2 * c2 + 1][r] = v.y;
    }
    __syncthreads();
    #pragma unroll
    for (int j = 0; j < 2; j++) {
        int idx = tid + 256 * j;
        int c  = idx >> 4;
        int rp = idx & 15;
        __nv_bfloat162 pk;
        pk.x = t[c][2 * rp]; pk.y = t[c][2 * rp + 1];
        *reinterpret_cast<__nv_bfloat162*>(dst + (long)(c0 + c) * L_SEQ + r0 + 2 * rp) = pk;
    }
}

__global__ void finalize_cols(const float* __restrict__ num, const float* __restrict__ den,
                              __nv_bfloat16* __restrict__ yc) {
    int idx = blockIdx.x * 256 + threadIdx.x;
    if (idx < 15 * L_SEQ) {
        int h = idx / L_SEQ, l = idx % L_SEQ;
        yc[(long)l * 256 + h] = __float2bfloat16(num[idx] / den[(long)h * L_SEQ + l]);
    }
}

__global__ void finalize15(const float* __restrict__ a15, const float* __restrict__ den15,
                           __nv_bfloat16* __restrict__ yc) {
    int idx = blockIdx.x * 256 + threadIdx.x;
    int l = idx >> 7, v = idx & 127;
    yc[(long)l * 256 + 15 + v] = __float2bfloat16(a15[idx] / den15[l]);
}

// ---------------- host launchers ----------------
static void launch_narrow(int epi, const GP& p, int M, int N, int Z) {
    dim3 grid(M / BM, N / BN, Z), block(256);
    switch (epi) {
        case 0: cudaFuncSetAttribute(gemm_bf16<0>, cudaFuncAttributeMaxDynamicSharedMemorySize, GEMM_SMEM);
                gemm_bf16<0><<<grid, block, GEMM_SMEM>>>(p); break;
        case 7: cudaFuncSetAttribute(gemm_bf16<7>, cudaFuncAttributeMaxDynamicSharedMemorySize, GEMM_SMEM);
                gemm_bf16<7><<<grid, block, GEMM_SMEM>>>(p); break;
    }
}
static void launch_wide(int epi, const GP& p, int M, int N, int Z) {
    dim3 grid(M / WBM, N / WBN, Z), block(256);
    switch (epi) {
        case 1: cudaFuncSetAttribute(gemm_wide<1>, cudaFuncAttributeMaxDynamicSharedMemorySize, WSMEM);
                gemm_wide<1><<<grid, block, WSMEM>>>(p); break;
        case 3: cudaFuncSetAttribute(gemm_wide<3>, cudaFuncAttributeMaxDynamicSharedMemorySize, WSMEM);
                gemm_wide<3><<<grid, block, WSMEM>>>(p); break;
        case 4: cudaFuncSetAttribute(gemm_wide<4>, cudaFuncAttributeMaxDynamicSharedMemorySize, WSMEM);
                gemm_wide<4><<<grid, block, WSMEM>>>(p); break;
        case 5: cudaFuncSetAttribute(gemm_wide<5>, cudaFuncAttributeMaxDynamicSharedMemorySize, WSMEM);
                gemm_wide<5><<<grid, block, WSMEM>>>(p); break;
        case 6: cudaFuncSetAttribute(gemm_wide<6>, cudaFuncAttributeMaxDynamicSharedMemorySize, WSMEM);
                gemm_wide<6><<<grid, block, WSMEM>>>(p); break;
        case 8: cudaFuncSetAttribute(gemm_wide<8>, cudaFuncAttributeMaxDynamicSharedMemorySize, WSMEM);
                gemm_wide<8><<<grid, block, WSMEM>>>(p); break;
    }
}

extern "C" void kernel_launch(void* const* d_in, const int* in_sizes, int n_in,
                              void* d_out, int out_size) {
    const float* x      = (const float*)d_in[0];
    const float* Wq     = (const float*)d_in[1];
    const float* bq     = (const float*)d_in[2];
    const float* Wk     = (const float*)d_in[3];
    const float* bk     = (const float*)d_in[4];
    const float* Wv     = (const float*)d_in[5];
    const float* bv     = (const float*)d_in[6];
    const float* Wo     = (const float*)d_in[7];
    const float* bo     = (const float*)d_in[8];
    const float* gamma1 = (const float*)d_in[9];
    const float* beta1  = (const float*)d_in[10];
    const float* gamma2 = (const float*)d_in[11];
    const float* beta2  = (const float*)d_in[12];
    const float* W1     = (const float*)d_in[13];
    const float* b1     = (const float*)d_in[14];
    const float* W2     = (const float*)d_in[15];
    const float* b2     = (const float*)d_in[16];
    float* out = (float*)d_out;

    void *p_xn1, *p_xn2, *p_xn2f, *p_x2, *p_Wqt, *p_Wkt, *p_Wv15t, *p_Wv0, *p_v0;
    void *p_q, *p_k, *p_v15, *p_v15t, *p_E15, *p_den, *p_num, *p_a15;
    void *p_yc, *p_Wot, *p_W1t, *p_W2t, *p_h1;
    cudaGetSymbolAddress(&p_xn1, g_xn1);   cudaGetSymbolAddress(&p_xn2, g_xn2);
    cudaGetSymbolAddress(&p_xn2f, g_xn2f); cudaGetSymbolAddress(&p_x2, g_x2);
    cudaGetSymbolAddress(&p_Wqt, g_Wqt);   cudaGetSymbolAddress(&p_Wkt, g_Wkt);
    cudaGetSymbolAddress(&p_Wv15t, g_Wv15t); cudaGetSymbolAddress(&p_Wv0, g_Wv0);
    cudaGetSymbolAddress(&p_v0, g_v0);     cudaGetSymbolAddress(&p_q, g_q);
    cudaGetSymbolAddress(&p_k, g_k);       cudaGetSymbolAddress(&p_v15, g_v15);
    cudaGetSymbolAddress(&p_v15t, g_v15t); cudaGetSymbolAddress(&p_E15, g_E15);
    cudaGetSymbolAddress(&p_den, g_den);   cudaGetSymbolAddress(&p_num, g_num);
    cudaGetSymbolAddress(&p_a15, g_a15);   cudaGetSymbolAddress(&p_yc, g_yc);
    cudaGetSymbolAddress(&p_Wot, g_Wot);   cudaGetSymbolAddress(&p_W1t, g_W1t);
    cudaGetSymbolAddress(&p_W2t, g_W2t);   cudaGetSymbolAddress(&p_h1, g_h1);

    __nv_bfloat16* xn1  = (__nv_bfloat16*)p_xn1;
    __nv_bfloat16* xn2  = (__nv_bfloat16*)p_xn2;
    float* xn2f = (float*)p_xn2f;
    float* x2   = (float*)p_x2;
    __nv_bfloat16* Wqt  = (__nv_bfloat16*)p_Wqt;
    __nv_bfloat16* Wkt  = (__nv_bfloat16*)p_Wkt;
    __nv_bfloat16* Wv15t= (__nv_bfloat16*)p_Wv15t;
    float* Wv0  = (float*)p_Wv0;
    float* v0   = (float*)p_v0;
    __nv_bfloat16* q    = (__nv_bfloat16*)p_q;
    __nv_bfloat16* k    = (__nv_bfloat16*)p_k;
    __nv_bfloat16* v15  = (__nv_bfloat16*)p_v15;
    __nv_bfloat16* v15t = (__nv_bfloat16*)p_v15t;
    __nv_bfloat16* E15  = (__nv_bfloat16*)p_E15;
    float* den  = (float*)p_den;
    float* num  = (float*)p_num;
    float* a15  = (float*)p_a15;
    __nv_bfloat16* yc   = (__nv_bfloat16*)p_yc;
    __nv_bfloat16* Wot  = (__nv_bfloat16*)p_Wot;
    __nv_bfloat16* W1t  = (__nv_bfloat16*)p_W1t;
    __nv_bfloat16* W2t  = (__nv_bfloat16*)p_W2t;
    __nv_bfloat16* h1   = (__nv_bfloat16*)p_h1;

    cudaMemsetAsync(den, 0, (size_t)NH * L_SEQ * sizeof(float));
    cudaMemsetAsync(num, 0, (size_t)15 * L_SEQ * sizeof(float));
    cudaMemsetAsync(a15, 0, (size_t)L_SEQ * DA * sizeof(float));
    cudaMemsetAsync(yc,  0, (size_t)L_SEQ * 256 * sizeof(__nv_bfloat16));

    transpose_cvt<<<dim3(DA/32, DE/64, NH), 256>>>(Wq, Wqt, DE, DA, (long)DE*DA, (long)DA*DE);
    transpose_cvt<<<dim3(DA/32, DE/64, NH), 256>>>(Wk, Wkt, DE, DA, (long)DE*DA, (long)DA*DE);
    transpose_cvt<<<dim3(DA/32, DE/64, 1),  256>>>(Wv + (long)15*DE*DA, Wv15t, DE, DA, 0, 0);
    transpose_cvt<<<dim3(DMLP/32, DE/64, 1), 256>>>(W1, W1t, DE, DMLP, 0, 0);
    transpose_cvt<<<dim3(DE/32, DMLP/64, 1), 256>>>(W2, W2t, DMLP, DE, 0, 0);
    wo_prep<<<(256 * DE) / 256, 256>>>(Wo, Wot);
    wv0_prep<<<(15 * DE + 255) / 256, 256>>>(Wv, Wv0);

    ln_kernel<<<L_SEQ, 256>>>(x, gamma1, beta1, xn1, nullptr);

    GP p{};
    const float inv_sqrt_d = 0.08838834764831845f;

    // ---- Q/K projections: wide kernel, head pairs (Z=8, N=256) ----
    p = GP{xn1, DE, 0, Wqt, DE, (long)256*DE, DE, bq, 0, q, DA, (long)L_SEQ*DA,
           nullptr, nullptr, nullptr, nullptr, nullptr, 0.f};
    launch_wide(8, p, L_SEQ, 256, 8);
    p = GP{xn1, DE, 0, Wkt, DE, (long)256*DE, DE, bk, 0, k, DA, (long)L_SEQ*DA,
           nullptr, nullptr, nullptr, nullptr, nullptr, 0.f};
    launch_wide(8, p, L_SEQ, 256, 8);

    // ---- V head 15 (narrow) ----
    p = GP{xn1, DE, 0, Wv15t, DE, 0, DE, bv + 15*DA, 0, v15, DA, 0,
           nullptr, nullptr, nullptr, nullptr, nullptr, 0.f};
    launch_narrow(0, p, L_SEQ, DA, 1);

    // ---- v0 matvecs ----
    cudaFuncSetAttribute(v0_kernel, cudaFuncAttributeMaxDynamicSharedMemorySize, 16*DE*2);
    v0_kernel<<<L_SEQ/16, 256, 16*DE*2>>>(xn1, Wv0, bv, v0);

    // ---- heads 0..14: fused exp + rowsum + v0-dot ----
    p = GP{q, DA, (long)L_SEQ*DA, k, DA, (long)L_SEQ*DA, DA, nullptr, 0,
           nullptr, 0, 0, nullptr, nullptr, den, num, v0, inv_sqrt_d};
    launch_wide(6, p, L_SEQ, L_SEQ, 15);

    // ---- head 15: E15 stored + rowsum ----
    p = GP{q + (long)15*L_SEQ*DA, DA, 0, k + (long)15*L_SEQ*DA, DA, 0, DA, nullptr, 0,
           E15, L_SEQ, 0, nullptr, nullptr, den + 15*L_SEQ, nullptr, nullptr, inv_sqrt_d};
    launch_wide(1, p, L_SEQ, L_SEQ, 1);

    finalize_cols<<<(15 * L_SEQ + 255) / 256, 256>>>(num, den, yc);

    // ---- A15 = E15 @ v15 (split-K, narrow) ----
    t_v15<<<dim3(DA/32, L_SEQ/32), 256>>>(v15, v15t);
    p = GP{E15, L_SEQ, 256, v15t, L_SEQ, 256, 256, nullptr, 0,
           a15, DA, 0, nullptr, nullptr, nullptr, nullptr, nullptr, 0.f};
    launch_narrow(7, p, L_SEQ, DA, 8);
    finalize15<<<(L_SEQ * DA) / 256, 256>>>(a15, den + 15*L_SEQ, yc);

    // ---- x2 = 2x + yc @ Wo' + bo ----
    p = GP{yc, 256, 0, Wot, 256, 0, 256, bo, 0, x2, DE, 0,
           x, nullptr, nullptr, nullptr, nullptr, 0.f};
    launch_wide(3, p, L_SEQ, DE, 1);

    ln_kernel<<<L_SEQ, 256>>>(x2, gamma2, beta2, xn2, xn2f);

    // ---- h1 = gelu(xn2 @ W1 + b1) ----
    p = GP{xn2, DE, 0, W1t, DE, 0, DE, b1, 0, h1, DMLP, 0,
           nullptr, nullptr, nullptr, nullptr, nullptr, 0.f};
    launch_wide(4, p, L_SEQ, DMLP, 1);

    // ---- out = h1 @ W2 + b2 + x2 + xn2 ----
    p = GP{h1, DMLP, 0, W2t, DMLP, 0, DMLP, b2, 0, out, DE, 0,
           x2, xn2f, nullptr, nullptr, nullptr, 0.f};
    launch_wide(5, p, L_SEQ, DE, 1);
}

// round 6
// speedup vs baseline: 1.1333x; 1.1333x over previous
#include <cuda_runtime.h>
#include <cuda_bf16.h>
#include <cstdint>

#define L_SEQ 2048
#define DE    2048
#define DMLP  8192
#define NH    16
#define DA    128

// narrow mma.sync kernel (128x128 tile)
#define BM 128
#define BN 128
#define BK 64
#define STAGE_BYTES (BM*128 + BN*128)
#define GEMM_SMEM   (3*STAGE_BYTES)

// tc kernel (128x256 tile)
#define TBM 128
#define TBN 256
#define TSTG ((TBM + TBN) * 128)          // 49152 bytes per stage
#define TSMEM (1024 + 3 * TSTG)           // 148480 bytes

// tcgen05 available only in arch-specific ('a') compilation passes
#if defined(__CUDA_ARCH_FEAT_SM103_ALL) || defined(__CUDA_ARCH_FEAT_SM100_ALL) || \
    defined(__CUDA_ARCH_FEAT_SM101_ALL) || defined(__CUDA_ARCH_SPECIFIC__)
#define HAS_TC 1
#else
#define HAS_TC 0
#endif

// ---------------- static device scratch (allocation-free) ----------------
static __device__ __align__(256) __nv_bfloat16 g_xn1 [(size_t)L_SEQ*DE];
static __device__ __align__(256) __nv_bfloat16 g_xn2 [(size_t)L_SEQ*DE];
static __device__ __align__(256) float         g_xn2f[(size_t)L_SEQ*DE];
static __device__ __align__(256) float         g_x2  [(size_t)L_SEQ*DE];
static __device__ __align__(256) __nv_bfloat16 g_Wqt [(size_t)NH*DA*DE];
static __device__ __align__(256) __nv_bfloat16 g_Wkt [(size_t)NH*DA*DE];
static __device__ __align__(256) __nv_bfloat16 g_Wv15t[(size_t)DA*DE];
static __device__ __align__(256) float         g_Wv0 [(size_t)15*DE];
static __device__ __align__(256) float         g_v0  [(size_t)15*L_SEQ];
static __device__ __align__(256) __nv_bfloat16 g_q   [(size_t)NH*L_SEQ*DA];
static __device__ __align__(256) __nv_bfloat16 g_k   [(size_t)NH*L_SEQ*DA];
static __device__ __align__(256) __nv_bfloat16 g_v15 [(size_t)L_SEQ*DA];
static __device__ __align__(256) __nv_bfloat16 g_v15t[(size_t)DA*L_SEQ];
static __device__ __align__(256) __nv_bfloat16 g_E15 [(size_t)L_SEQ*L_SEQ];
static __device__ __align__(256) float         g_den [(size_t)NH*L_SEQ];
static __device__ __align__(256) float         g_num [(size_t)15*L_SEQ];
static __device__ __align__(256) float         g_a15 [(size_t)L_SEQ*DA];
static __device__ __align__(256) __nv_bfloat16 g_yc  [(size_t)L_SEQ*256];
static __device__ __align__(256) __nv_bfloat16 g_Wot [(size_t)DE*256];
static __device__ __align__(256) __nv_bfloat16 g_W1t [(size_t)DMLP*DE];
static __device__ __align__(256) __nv_bfloat16 g_W2t [(size_t)DE*DMLP];
static __device__ __align__(256) __nv_bfloat16 g_h1  [(size_t)L_SEQ*DMLP];

// ---------------- generic helpers ----------------
__device__ __forceinline__ void cpasync16(uint32_t dst, const void* src) {
    asm volatile("cp.async.cg.shared.global [%0], [%1], 16;\n" :: "r"(dst), "l"(src));
}
__device__ __forceinline__ void cpcommit() { asm volatile("cp.async.commit_group;\n"); }
template<int N> __device__ __forceinline__ void cpwait() {
    asm volatile("cp.async.wait_group %0;\n" :: "n"(N));
}
__device__ __forceinline__ void ldsm4(uint32_t* r, uint32_t addr) {
    asm volatile("ldmatrix.sync.aligned.m8n8.x4.shared.b16 {%0,%1,%2,%3}, [%4];\n"
                 : "=r"(r[0]), "=r"(r[1]), "=r"(r[2]), "=r"(r[3]) : "r"(addr));
}
__device__ __forceinline__ void mma16816(float* c, const uint32_t* a, uint32_t b0, uint32_t b1) {
    asm volatile("mma.sync.aligned.m16n8k16.row.col.f32.bf16.bf16.f32 "
                 "{%0,%1,%2,%3}, {%4,%5,%6,%7}, {%8,%9}, {%0,%1,%2,%3};\n"
                 : "+f"(c[0]), "+f"(c[1]), "+f"(c[2]), "+f"(c[3])
                 : "r"(a[0]), "r"(a[1]), "r"(a[2]), "r"(a[3]), "r"(b0), "r"(b1));
}
__device__ __forceinline__ float fast_exp(float t) {
    if (fabsf(t) < 0.25f) return 1.f + t * (1.f + t * (0.5f + t * 0.16666667f));
    return expf(t);
}
__device__ __forceinline__ float gelu_tanh(float u) {
    float u2 = u * u;
    float w  = 0.7978845608028654f * u * (1.f + 0.044715f * u2);
    float t;
    if (fabsf(w) < 0.5f) {
        float w2 = w * w;
        t = w * (1.f - w2 * (0.33333333f - w2 * (0.13333333f - w2 * 0.05396825f)));
    } else {
        t = tanhf(w);
    }
    return 0.5f * u * (1.f + t);
}
__device__ __forceinline__ uint32_t smem_u32(const void* p) {
    return (uint32_t)__cvta_generic_to_shared(p);
}
__device__ __forceinline__ uint32_t elect_one() {
    uint32_t pred;
    asm volatile("{\n\t.reg .pred p;\n\telect.sync _|p, 0xFFFFFFFF;\n\t"
                 "selp.b32 %0, 1, 0, p;\n\t}" : "=r"(pred));
    return pred;
}

#if HAS_TC
// ---------------- tcgen05 helpers (only compiled for 'a' targets) ----------------
__device__ __forceinline__ void tc_alloc(uint32_t smem_dst, uint32_t ncols) {
    asm volatile("tcgen05.alloc.cta_group::1.sync.aligned.shared::cta.b32 [%0], %1;"
                 :: "r"(smem_dst), "r"(ncols) : "memory");
}
__device__ __forceinline__ void tc_relinq() {
    asm volatile("tcgen05.relinquish_alloc_permit.cta_group::1.sync.aligned;");
}
__device__ __forceinline__ void tc_dealloc(uint32_t tmem, uint32_t ncols) {
    asm volatile("tcgen05.dealloc.cta_group::1.sync.aligned.b32 %0, %1;" :: "r"(tmem), "r"(ncols));
}
__device__ __forceinline__ void tc_commit(uint32_t mbar) {
    asm volatile("tcgen05.commit.cta_group::1.mbarrier::arrive::one.shared::cluster.b64 [%0];"
                 :: "r"(mbar) : "memory");
}
__device__ __forceinline__ void tc_fence_after() {
    asm volatile("tcgen05.fence::after_thread_sync;" ::: "memory");
}
__device__ __forceinline__ void fence_proxy() {
    asm volatile("fence.proxy.async.shared::cta;" ::: "memory");
}
__device__ __forceinline__ void mbar_init(uint32_t a, uint32_t cnt) {
    asm volatile("mbarrier.init.shared.b64 [%0], %1;" :: "r"(a), "r"(cnt) : "memory");
}
__device__ __forceinline__ void mbar_wait(uint32_t a, uint32_t parity) {
    asm volatile(
        "{\n\t.reg .pred P;\n"
        "W%=:\n\t"
        "mbarrier.try_wait.parity.shared.b64 P, [%0], %1;\n\t"
        "@!P bra W%=;\n\t}"
        :: "r"(a), "r"(parity) : "memory");
}
__device__ __forceinline__ void tcmma_f16_ss(uint32_t d, uint64_t ad, uint64_t bd,
                                             uint32_t idesc, uint32_t en) {
    asm volatile(
        "{\n\t.reg .pred p;\n\t"
        "setp.ne.u32 p, %5, 0;\n\t"
        "tcgen05.mma.cta_group::1.kind::f16 [%0], %1, %2, %3, {%4, %4, %4, %4}, p;\n\t}"
        :: "r"(d), "l"(ad), "l"(bd), "r"(idesc), "r"(0u), "r"(en) : "memory");
}
__device__ __forceinline__ void tc_ld32(uint32_t* r, uint32_t tmem) {
    asm volatile(
        "tcgen05.ld.sync.aligned.32x32b.x32.b32 "
        "{%0, %1, %2, %3, %4, %5, %6, %7, "
        " %8, %9, %10, %11, %12, %13, %14, %15, "
        " %16, %17, %18, %19, %20, %21, %22, %23, "
        " %24, %25, %26, %27, %28, %29, %30, %31}, [%32];"
        : "=r"(r[0]), "=r"(r[1]), "=r"(r[2]), "=r"(r[3]),
          "=r"(r[4]), "=r"(r[5]), "=r"(r[6]), "=r"(r[7]),
          "=r"(r[8]), "=r"(r[9]), "=r"(r[10]), "=r"(r[11]),
          "=r"(r[12]), "=r"(r[13]), "=r"(r[14]), "=r"(r[15]),
          "=r"(r[16]), "=r"(r[17]), "=r"(r[18]), "=r"(r[19]),
          "=r"(r[20]), "=r"(r[21]), "=r"(r[22]), "=r"(r[23]),
          "=r"(r[24]), "=r"(r[25]), "=r"(r[26]), "=r"(r[27]),
          "=r"(r[28]), "=r"(r[29]), "=r"(r[30]), "=r"(r[31])
        : "r"(tmem));
}
__device__ __forceinline__ void tc_wait_ld() {
    asm volatile("tcgen05.wait::ld.sync.aligned;" ::: "memory");
}
// 64-bit SMEM descriptor: SW128, version 1 (Blackwell), LBO=1, SBO=64
static __device__ __forceinline__ uint64_t make_desc(uint32_t addr) {
    const uint64_t base =
        (uint64_t(2)  << 61) | (uint64_t(1) << 46) |
        (uint64_t(64) << 32) | (uint64_t(1) << 16);
    return base | ((uint64_t)(addr >> 4) & 0x3FFF);
}
// idesc kind::f16: F32 accum, BF16 x BF16, M=128, N=256 (cg1)
#define TC_IDESC ((1u<<4) | (1u<<7) | (1u<<10) | ((TBN/8)<<17) | ((TBM/16)<<24))
#endif // HAS_TC

// Epilogue numbering:
// 0: bf16 C = acc + bias[n]                          (narrow)
// 1: bf16 C = exp(acc*scale), den rowsum atomics     (tc, head 15)
// 3: f32  C = 2*aux1 + acc + bias[n]                 (narrow, Wo)
// 4: bf16 C = gelu(acc + bias[n])                    (tc, MLP1)
// 5: f32  C = acc + bias[n] + aux1 + aux2            (tc, MLP2)
// 6: no store; den/num atomics with v0 dot           (tc, heads 0..14)
// 7: atomicAdd f32 C += acc                          (narrow, split-K A15)
// 8: bf16 head-pair split store                      (tc, Q/K proj)
struct GP {
    const __nv_bfloat16* A; int lda; long sA;
    const __nv_bfloat16* B; int ldb; long sB;
    int K;
    const float* bias; int sBias;
    void* C; int ldc; long sC;
    const float* aux1;
    const float* aux2;
    float* den;
    float* num;
    const float* v0;
    float scale;
};

// ---------------- narrow mma.sync GEMM: 128x128 tile, 32x64 warp tile ----------------
template<int EPI>
__global__ void __launch_bounds__(256) gemm_bf16(GP p) {
    extern __shared__ __align__(128) char smem[];
    const int tid = threadIdx.x;
    const int bm = blockIdx.x * BM;
    const int bn = blockIdx.y * BN;
    const int z  = blockIdx.z;

    const __nv_bfloat16* Ag = p.A + (long)z * p.sA;
    const __nv_bfloat16* Bg = p.B + (long)z * p.sB;

    uint32_t sbase = smem_u32(smem);
    const int lr = tid >> 3, lc = tid & 7;
    const __nv_bfloat16* Agp = Ag + (long)(bm + lr) * p.lda + lc * 8;
    const __nv_bfloat16* Bgp = Bg + (long)(bn + lr) * p.ldb + lc * 8;

    float c[2][8][4];
    #pragma unroll
    for (int i = 0; i < 2; i++)
        #pragma unroll
        for (int j = 0; j < 8; j++)
            #pragma unroll
            for (int r = 0; r < 4; r++) c[i][j][r] = 0.f;

    const int KT = p.K / BK;

    auto issue = [&](int kt, int s) {
        uint32_t aS = sbase + s * STAGE_BYTES;
        uint32_t bS = aS + BM * 128;
        const __nv_bfloat16* Ak = Agp + kt * BK;
        const __nv_bfloat16* Bk = Bgp + kt * BK;
        #pragma unroll
        for (int i = 0; i < 4; i++) {
            int r = lr + 32 * i;
            cpasync16(aS + r * 128 + ((lc * 16) ^ ((r & 7) * 16)), Ak + (long)(32 * i) * p.lda);
        }
        #pragma unroll
        for (int i = 0; i < 4; i++) {
            int r = lr + 32 * i;
            cpasync16(bS + r * 128 + ((lc * 16) ^ ((r & 7) * 16)), Bk + (long)(32 * i) * p.ldb);
        }
        cpcommit();
    };

    issue(0, 0);
    if (KT > 1) issue(1, 1);

    const int lane = tid & 31, warp = tid >> 5;
    const int wm = warp & 3, wn = warp >> 2;

    for (int kt = 0; kt < KT; kt++) {
        if (kt < KT - 1) cpwait<1>(); else cpwait<0>();
        __syncthreads();
        if (kt + 2 < KT) issue(kt + 2, (kt + 2) % 3);

        uint32_t aS = sbase + (kt % 3) * STAGE_BYTES;
        uint32_t bS = aS + BM * 128;
        #pragma unroll
        for (int ks = 0; ks < 4; ks++) {
            uint32_t a[2][4];
            #pragma unroll
            for (int i = 0; i < 2; i++) {
                int r  = wm * 32 + i * 16 + (lane & 15);
                int cb = ks * 32 + ((lane >> 4) << 4);
                ldsm4(a[i], aS + r * 128 + (cb ^ ((r & 7) << 4)));
            }
            #pragma unroll
            for (int j4 = 0; j4 < 4; j4++) {
                uint32_t b[4];
                int n  = wn * 64 + j4 * 16 + ((lane >> 4) << 3) + (lane & 7);
                int cb = ks * 32 + (((lane >> 3) & 1) << 4);
                ldsm4(b, bS + n * 128 + (cb ^ ((n & 7) << 4)));
                #pragma unroll
                for (int i = 0; i < 2; i++) {
                    mma16816(c[i][2 * j4],     a[i], b[0], b[1]);
                    mma16816(c[i][2 * j4 + 1], a[i], b[2], b[3]);
                }
            }
        }
    }

    const int row0 = lane >> 2, col0 = (lane & 3) * 2;
    #pragma unroll
    for (int i = 0; i < 2; i++)
        #pragma unroll
        for (int j = 0; j < 8; j++)
            #pragma unroll
            for (int h2 = 0; h2 < 2; h2++) {
                long gm = bm + wm * 32 + i * 16 + h2 * 8 + row0;
                long gn = bn + wn * 64 + j * 8 + col0;
                float a0 = c[i][j][h2 * 2 + 0];
                float a1 = c[i][j][h2 * 2 + 1];
                if (EPI == 0) {
                    __nv_bfloat16* C = (__nv_bfloat16*)p.C + (long)z * p.sC;
                    float x0 = a0 + p.bias[gn], x1 = a1 + p.bias[gn + 1];
                    __nv_bfloat162 pk;
                    pk.x = __float2bfloat16(x0); pk.y = __float2bfloat16(x1);
                    *reinterpret_cast<__nv_bfloat162*>(&C[gm * p.ldc + gn]) = pk;
                } else if (EPI == 3) {
                    float* C = (float*)p.C;
                    long i0 = gm * p.ldc + gn;
                    C[i0]     = 2.f * p.aux1[i0]     + a0 + p.bias[gn];
                    C[i0 + 1] = 2.f * p.aux1[i0 + 1] + a1 + p.bias[gn + 1];
                } else if (EPI == 7) {
                    float* C = (float*)p.C;
                    long i0 = gm * p.ldc + gn;
                    atomicAdd(&C[i0],     a0);
                    atomicAdd(&C[i0 + 1], a1);
                }
            }
}

// ---------------- tc GEMM: 128x256 tile ----------------
// tcgen05 path on 'a' targets; mma.sync wide fallback otherwise.
template<int EPI>
__global__ void __launch_bounds__(256, 1) gemm_tc(GP p) {
    extern __shared__ __align__(1024) char smem[];
    uint32_t sb = smem_u32(smem);
    const int tid = threadIdx.x, warp = tid >> 5, lane = tid & 31;
    const int bm = blockIdx.x * TBM;
    const int bn = blockIdx.y * TBN;
    const int z  = blockIdx.z;

    const __nv_bfloat16* Ag = p.A + (long)z * p.sA;
    const __nv_bfloat16* Bg = p.B + (long)z * p.sB;

    const int lr = tid >> 3, lc = tid & 7;
    const __nv_bfloat16* Agp = Ag + (long)(bm + lr) * p.lda + lc * 8;
    const __nv_bfloat16* Bgp = Bg + (long)(bn + lr) * p.ldb + lc * 8;

    const int KT = p.K / BK;

    auto issue = [&](int kt, int s) {
        uint32_t aS = sb + 1024 + s * TSTG;
        uint32_t bS = aS + TBM * 128;
        const __nv_bfloat16* Ak = Agp + kt * BK;
        const __nv_bfloat16* Bk = Bgp + kt * BK;
        #pragma unroll
        for (int i = 0; i < 4; i++) {
            int r = lr + 32 * i;
            cpasync16(aS + r * 128 + ((lc * 16) ^ ((r & 7) * 16)), Ak + (long)(32 * i) * p.lda);
        }
        #pragma unroll
        for (int i = 0; i < 8; i++) {
            int r = lr + 32 * i;
            cpasync16(bS + r * 128 + ((lc * 16) ^ ((r & 7) * 16)), Bk + (long)(32 * i) * p.ldb);
        }
        cpcommit();
    };

#if HAS_TC
    // ---- tcgen05 path ----
    if (warp == 0) { tc_alloc(sb, 256); tc_relinq(); }
    if (tid == 0) { mbar_init(sb + 16, 1); mbar_init(sb + 24, 1); mbar_init(sb + 32, 1); }
    __syncthreads();
    uint32_t tmem;
    asm volatile("ld.shared.b32 %0, [%1];" : "=r"(tmem) : "r"(sb));

    issue(0, 0);
    if (KT > 1) issue(1, 1);

    int wcnt0 = 0, wcnt1 = 0, wcnt2 = 0;

    for (int kt = 0; kt < KT; kt++) {
        if (kt < KT - 1) cpwait<1>(); else cpwait<0>();
        __syncthreads();

        if (warp == 0 && elect_one()) {
            fence_proxy();
            uint32_t aS = sb + 1024 + (kt % 3) * TSTG;
            uint32_t bS = aS + TBM * 128;
            uint64_t ad = make_desc(aS), bd = make_desc(bS);
            #pragma unroll
            for (int ks = 0; ks < 4; ks++)
                tcmma_f16_ss(tmem, ad + ks * 2, bd + ks * 2, TC_IDESC,
                             (kt == 0 && ks == 0) ? 0u : 1u);
            tc_commit(sb + 16 + 8 * (kt % 3));
        }

        int nx = kt + 2;
        if (nx < KT) {
            int s = nx % 3;
            if (nx >= 3) {
                if (s == 0)      { mbar_wait(sb + 16, wcnt0 & 1); wcnt0++; }
                else if (s == 1) { mbar_wait(sb + 24, wcnt1 & 1); wcnt1++; }
                else             { mbar_wait(sb + 32, wcnt2 & 1); wcnt2++; }
            }
            issue(nx, s);
        }
    }

    {
        int s = (KT - 1) % 3;
        if (s == 0)      mbar_wait(sb + 16, wcnt0 & 1);
        else if (s == 1) mbar_wait(sb + 24, wcnt1 & 1);
        else             mbar_wait(sb + 32, wcnt2 & 1);
    }
    tc_fence_after();

    if (warp < 4) {
        long gm = bm + warp * 32 + lane;
        float se = 0.f, sn = 0.f;
        const float* vv = (EPI == 6) ? (p.v0 + (long)z * L_SEQ) : nullptr;

        #pragma unroll
        for (int cb = 0; cb < 8; cb++) {
            uint32_t r[32];
            tc_ld32(r, tmem + cb * 32);
            tc_wait_ld();

            if (EPI == 4) {
                __nv_bfloat16* C = (__nv_bfloat16*)p.C;
                #pragma unroll
                for (int j = 0; j < 32; j += 2) {
                    long gn = bn + cb * 32 + j;
                    float x0 = gelu_tanh(__uint_as_float(r[j])     + p.bias[gn]);
                    float x1 = gelu_tanh(__uint_as_float(r[j + 1]) + p.bias[gn + 1]);
                    __nv_bfloat162 pk;
                    pk.x = __float2bfloat16(x0); pk.y = __float2bfloat16(x1);
                    *reinterpret_cast<__nv_bfloat162*>(&C[gm * p.ldc + gn]) = pk;
                }
            } else if (EPI == 5) {
                float* C = (float*)p.C;
                #pragma unroll
                for (int j = 0; j < 32; j++) {
                    long gn = bn + cb * 32 + j;
                    long i0 = gm * p.ldc + gn;
                    C[i0] = __uint_as_float(r[j]) + p.bias[gn] + p.aux1[i0] + p.aux2[i0];
                }
            } else if (EPI == 8) {
                #pragma unroll
                for (int j = 0; j < 32; j += 2) {
                    int gl = cb * 32 + j;
                    int head = z * 2 + (gl >> 7);
                    int col  = gl & 127;
                    __nv_bfloat16* C = (__nv_bfloat16*)p.C + (long)head * p.sC;
                    float x0 = __uint_as_float(r[j])     + p.bias[head * DA + col];
                    float x1 = __uint_as_float(r[j + 1]) + p.bias[head * DA + col + 1];
                    __nv_bfloat162 pk;
                    pk.x = __float2bfloat16(x0); pk.y = __float2bfloat16(x1);
                    *reinterpret_cast<__nv_bfloat162*>(&C[gm * DA + col]) = pk;
                }
            } else if (EPI == 6) {
                #pragma unroll
                for (int j = 0; j < 32; j++) {
                    long gn = bn + cb * 32 + j;
                    float e = fast_exp(__uint_as_float(r[j]) * p.scale);
                    se += e;
                    sn += e * vv[gn];
                }
            } else if (EPI == 1) {
                __nv_bfloat16* C = (__nv_bfloat16*)p.C;
                #pragma unroll
                for (int j = 0; j < 32; j += 2) {
                    long gn = bn + cb * 32 + j;
                    float e0 = fast_exp(__uint_as_float(r[j])     * p.scale);
                    float e1 = fast_exp(__uint_as_float(r[j + 1]) * p.scale);
                    se += e0 + e1;
                    __nv_bfloat162 pk;
                    pk.x = __float2bfloat16(e0); pk.y = __float2bfloat16(e1);
                    *reinterpret_cast<__nv_bfloat162*>(&C[gm * p.ldc + gn]) = pk;
                }
            }
        }
        if (EPI == 6) {
            atomicAdd(&p.den[(long)z * L_SEQ + gm], se);
            atomicAdd(&p.num[(long)z * L_SEQ + gm], sn);
        } else if (EPI == 1) {
            atomicAdd(&p.den[gm], se);
        }
    }

    __syncthreads();
    if (warp == 0) tc_dealloc(tmem, 256);

#else
    // ---- mma.sync wide fallback (compute_103 pass; correct, slower) ----
    float c[4][8][4];
    #pragma unroll
    for (int i = 0; i < 4; i++)
        #pragma unroll
        for (int j = 0; j < 8; j++)
            #pragma unroll
            for (int r = 0; r < 4; r++) c[i][j][r] = 0.f;

    issue(0, 0);
    if (KT > 1) issue(1, 1);

    const int wm = warp & 1, wn = warp >> 1;   // 2 x 4

    for (int kt = 0; kt < KT; kt++) {
        if (kt < KT - 1) cpwait<1>(); else cpwait<0>();
        __syncthreads();
        if (kt + 2 < KT) issue(kt + 2, (kt + 2) % 3);

        uint32_t aS = sb + 1024 + (kt % 3) * TSTG;
        uint32_t bS = aS + TBM * 128;
        #pragma unroll
        for (int ks = 0; ks < 4; ks++) {
            uint32_t a[4][4];
            #pragma unroll
            for (int i = 0; i < 4; i++) {
                int r  = wm * 64 + i * 16 + (lane & 15);
                int cb = ks * 32 + ((lane >> 4) << 4);
                ldsm4(a[i], aS + r * 128 + (cb ^ ((r & 7) << 4)));
            }
            #pragma unroll
            for (int j4 = 0; j4 < 4; j4++) {
                uint32_t b[4];
                int n  = wn * 64 + j4 * 16 + ((lane >> 4) << 3) + (lane & 7);
                int cb = ks * 32 + (((lane >> 3) & 1) << 4);
                ldsm4(b, bS + n * 128 + (cb ^ ((n & 7) << 4)));
                #pragma unroll
                for (int i = 0; i < 4; i++) {
                    mma16816(c[i][2 * j4],     a[i], b[0], b[1]);
                    mma16816(c[i][2 * j4 + 1], a[i], b[2], b[3]);
                }
            }
        }
    }

    const int row0 = lane >> 2, col0 = (lane & 3) * 2;

    if (EPI == 1 || EPI == 6) {
        const float* vv = (EPI == 6) ? (p.v0 + (long)z * L_SEQ) : nullptr;
        __nv_bfloat16* C = (__nv_bfloat16*)p.C;
        #pragma unroll
        for (int i = 0; i < 4; i++)
            #pragma unroll
            for (int h2 = 0; h2 < 2; h2++) {
                long gm = bm + wm * 64 + i * 16 + h2 * 8 + row0;
                float se = 0.f, sn = 0.f;
                #pragma unroll
                for (int j = 0; j < 8; j++) {
                    long gn = bn + wn * 64 + j * 8 + col0;
                    float e0 = fast_exp(c[i][j][h2 * 2 + 0] * p.scale);
                    float e1 = fast_exp(c[i][j][h2 * 2 + 1] * p.scale);
                    se += e0 + e1;
                    if (EPI == 6) sn += e0 * vv[gn] + e1 * vv[gn + 1];
                    if (EPI == 1) {
                        __nv_bfloat162 pk;
                        pk.x = __float2bfloat16(e0); pk.y = __float2bfloat16(e1);
                        *reinterpret_cast<__nv_bfloat162*>(&C[gm * p.ldc + gn]) = pk;
                    }
                }
                se += __shfl_xor_sync(0xffffffffu, se, 1);
                se += __shfl_xor_sync(0xffffffffu, se, 2);
                if (EPI == 6) {
                    sn += __shfl_xor_sync(0xffffffffu, sn, 1);
                    sn += __shfl_xor_sync(0xffffffffu, sn, 2);
                }
                if ((lane & 3) == 0) {
                    if (EPI == 1) atomicAdd(&p.den[gm], se);
                    else {
                        atomicAdd(&p.den[(long)z * L_SEQ + gm], se);
                        atomicAdd(&p.num[(long)z * L_SEQ + gm], sn);
                    }
                }
            }
        return;
    }

    #pragma unroll
    for (int i = 0; i < 4; i++)
        #pragma unroll
        for (int j = 0; j < 8; j++)
            #pragma unroll
            for (int h2 = 0; h2 < 2; h2++) {
                long gm = bm + wm * 64 + i * 16 + h2 * 8 + row0;
                long gn = bn + wn * 64 + j * 8 + col0;
                float a0 = c[i][j][h2 * 2 + 0];
                float a1 = c[i][j][h2 * 2 + 1];
                if (EPI == 4) {
                    __nv_bfloat16* C = (__nv_bfloat16*)p.C;
                    float x0 = gelu_tanh(a0 + p.bias[gn]);
                    float x1 = gelu_tanh(a1 + p.bias[gn + 1]);
                    __nv_bfloat162 pk;
                    pk.x = __float2bfloat16(x0); pk.y = __float2bfloat16(x1);
                    *reinterpret_cast<__nv_bfloat162*>(&C[gm * p.ldc + gn]) = pk;
                } else if (EPI == 5) {
                    float* C = (float*)p.C;
                    long i0 = gm * p.ldc + gn;
                    C[i0]     = a0 + p.bias[gn]     + p.aux1[i0]     + p.aux2[i0];
                    C[i0 + 1] = a1 + p.bias[gn + 1] + p.aux1[i0 + 1] + p.aux2[i0 + 1];
                } else if (EPI == 8) {
                    int head = z * 2 + (int)(gn >> 7);
                    int col  = (int)(gn & 127);
                    __nv_bfloat16* C = (__nv_bfloat16*)p.C + (long)head * p.sC;
                    float x0 = a0 + p.bias[head * DA + col];
                    float x1 = a1 + p.bias[head * DA + col + 1];
                    __nv_bfloat162 pk;
                    pk.x = __float2bfloat16(x0); pk.y = __float2bfloat16(x1);
                    *reinterpret_cast<__nv_bfloat162*>(&C[gm * DA + col]) = pk;
                }
            }
#endif
}

// ---------------- layernorm (population std) ----------------
__global__ void ln_kernel(const float* __restrict__ x, const float* __restrict__ g,
                          const float* __restrict__ b, __nv_bfloat16* ob, float* of) {
    int l = blockIdx.x, tid = threadIdx.x;
    const float* row = x + (long)l * DE;
    float v[8], s = 0.f, s2 = 0.f;
    #pragma unroll
    for (int j = 0; j < 8; j++) {
        v[j] = row[tid + 256 * j];
        s += v[j]; s2 += v[j] * v[j];
    }
    __shared__ float sm[18];
    #pragma unroll
    for (int o = 16; o; o >>= 1) {
        s  += __shfl_xor_sync(0xffffffffu, s,  o);
        s2 += __shfl_xor_sync(0xffffffffu, s2, o);
    }
    if ((tid & 31) == 0) { sm[tid >> 5] = s; sm[(tid >> 5) + 8] = s2; }
    __syncthreads();
    if (tid == 0) {
        float a = 0.f, q = 0.f;
        #pragma unroll
        for (int i = 0; i < 8; i++) { a += sm[i]; q += sm[i + 8]; }
        float mean = a / DE;
        float var  = q / DE - mean * mean;
        float sd   = sqrtf(fmaxf(var, 0.f));
        if (sd == 0.f) sd = 1.f;
        sm[16] = mean; sm[17] = 1.f / sd;
    }
    __syncthreads();
    float mean = sm[16], rs = sm[17];
    #pragma unroll
    for (int j = 0; j < 8; j++) {
        int col = tid + 256 * j;
        float y = g[col] * ((v[j] - mean) * rs) + b[col];
        ob[(long)l * DE + col] = __float2bfloat16(y);
        if (of) of[(long)l * DE + col] = y;
    }
}

// ---------------- v0 matvecs, tiled: 16 rows per block ----------------
__global__ void v0_kernel(const __nv_bfloat16* __restrict__ xn1, const float* __restrict__ Wv0,
                          const float* __restrict__ bv, float* __restrict__ v0) {
    extern __shared__ __nv_bfloat16 xr[];   // [16][2048]
    int l0 = blockIdx.x * 16, tid = threadIdx.x;
    const uint4* src = reinterpret_cast<const uint4*>(xn1 + (long)l0 * DE);
    uint4* dst = reinterpret_cast<uint4*>(xr);
    for (int i = tid; i < 16 * DE / 8; i += 256) dst[i] = src[i];
    __syncthreads();
    int lane = tid & 31, warp = tid >> 5;
    for (int task = warp; task < 15 * 16; task += 8) {
        int h = task / 16, l = task % 16;
        const float* w = Wv0 + (long)h * DE;
        const __nv_bfloat16* xrow = xr + (long)l * DE;
        float acc = 0.f;
        for (int k2 = lane; k2 < DE / 2; k2 += 32) {
            float2 xv = __bfloat1622float2(
                *reinterpret_cast<const __nv_bfloat162*>(xrow + 2 * k2));
            acc += xv.x * w[2 * k2] + xv.y * w[2 * k2 + 1];
        }
        #pragma unroll
        for (int o = 16; o; o >>= 1) acc += __shfl_xor_sync(0xffffffffu, acc, o);
        if (lane == 0) v0[(long)h * L_SEQ + l0 + l] = acc + bv[h * DA];
    }
}

// ---------------- weight prep ----------------
__global__ void transpose_cvt(const float* __restrict__ src, __nv_bfloat16* __restrict__ dst,
                              int R, int C, long sS, long sD) {
    __shared__ float t[32][65];
    src += (long)blockIdx.z * sS;
    dst += (long)blockIdx.z * sD;
    int c0 = blockIdx.x * 32, r0 = blockIdx.y * 64;
    int tid = threadIdx.x;
    #pragma unroll
    for (int j = 0; j < 2; j++) {
        int idx = tid + 256 * j;
        int r   = idx >> 3;
        int c4  = idx & 7;
        float4 v = *reinterpret_cast<const float4*>(src + (long)(r0 + r) * C + c0 + c4 * 4);
        t[c4 * 4 + 0][r] = v.x; t[c4 * 4 + 1][r] = v.y;
        t[c4 * 4 + 2][r] = v.z; t[c4 * 4 + 3][r] = v.w;
    }
    __syncthreads();
    #pragma unroll
    for (int j = 0; j < 4; j++) {
        int idx = tid + 256 * j;
        int c   = idx >> 5;
        int rp  = idx & 31;
        __nv_bfloat162 pk;
        pk.x = __float2bfloat16(t[c][2 * rp]);
        pk.y = __float2bfloat16(t[c][2 * rp + 1]);
        *reinterpret_cast<__nv_bfloat162*>(dst + (long)(c0 + c) * R + r0 + 2 * rp) = pk;
    }
}

__global__ void wo_prep(const float* __restrict__ Wo, __nv_bfloat16* __restrict__ Wot) {
    long idx = (long)blockIdx.x * 256 + threadIdx.x;
    int k = (int)(idx >> 11), n = (int)(idx & 2047);
    float v = (k < 143) ? Wo[(long)k * DE + n] : 0.f;
    Wot[(long)n * 256 + k] = __float2bfloat16(v);
}

__global__ void wv0_prep(const float* __restrict__ Wv, float* __restrict__ Wv0) {
    long idx = (long)blockIdx.x * 256 + threadIdx.x;
    if (idx < 15 * DE) {
        long h = idx / DE, k = idx % DE;
        Wv0[idx] = Wv[(h * DE + k) * DA];
    }
}

__global__ void t_v15(const __nv_bfloat16* __restrict__ src, __nv_bfloat16* __restrict__ dst) {
    __shared__ __nv_bfloat16 t[32][34];
    int c0 = blockIdx.x * 32;
    int r0 = blockIdx.y * 32;
    int tid = threadIdx.x;
    #pragma unroll
    for (int j = 0; j < 2; j++) {
        int idx = tid + 256 * j;
        int r  = idx >> 4;
        int c2 = idx & 15;
        __nv_bfloat162 v = *reinterpret_cast<const __nv_bfloat162*>(
            src + (long)(r0 + r) * DA + c0 + 2 * c2);
        t[2 * c2][r] = v.x; t[2 * c2 + 1][r] = v.y;
    }
    __syncthreads();
    #pragma unroll
    for (int j = 0; j < 2; j++) {
        int idx = tid + 256 * j;
        int c  = idx >> 4;
        int rp = idx & 15;
        __nv_bfloat162 pk;
        pk.x = t[c][2 * rp]; pk.y = t[c][2 * rp + 1];
        *reinterpret_cast<__nv_bfloat162*>(dst + (long)(c0 + c) * L_SEQ + r0 + 2 * rp) = pk;
    }
}

__global__ void finalize_cols(const float* __restrict__ num, const float* __restrict__ den,
                              __nv_bfloat16* __restrict__ yc) {
    int idx = blockIdx.x * 256 + threadIdx.x;
    if (idx < 15 * L_SEQ) {
        int h = idx / L_SEQ, l = idx % L_SEQ;
        yc[(long)l * 256 + h] = __float2bfloat16(num[idx] / den[(long)h * L_SEQ + l]);
    }
}

__global__ void finalize15(const float* __restrict__ a15, const float* __restrict__ den15,
                           __nv_bfloat16* __restrict__ yc) {
    int idx = blockIdx.x * 256 + threadIdx.x;
    int l = idx >> 7, v = idx & 127;
    yc[(long)l * 256 + 15 + v] = __float2bfloat16(a15[idx] / den15[l]);
}

// ---------------- host launchers ----------------
static void launch_narrow(int epi, const GP& p, int M, int N, int Z) {
    dim3 grid(M / BM, N / BN, Z), block(256);
    switch (epi) {
        case 0: cudaFuncSetAttribute(gemm_bf16<0>, cudaFuncAttributeMaxDynamicSharedMemorySize, GEMM_SMEM);
                gemm_bf16<0><<<grid, block, GEMM_SMEM>>>(p); break;
        case 3: cudaFuncSetAttribute(gemm_bf16<3>, cudaFuncAttributeMaxDynamicSharedMemorySize, GEMM_SMEM);
                gemm_bf16<3><<<grid, block, GEMM_SMEM>>>(p); break;
        case 7: cudaFuncSetAttribute(gemm_bf16<7>, cudaFuncAttributeMaxDynamicSharedMemorySize, GEMM_SMEM);
                gemm_bf16<7><<<grid, block, GEMM_SMEM>>>(p); break;
    }
}
static void launch_tc(int epi, const GP& p, int M, int N, int Z) {
    dim3 grid(M / TBM, N / TBN, Z), block(256);
    switch (epi) {
        case 1: cudaFuncSetAttribute(gemm_tc<1>, cudaFuncAttributeMaxDynamicSharedMemorySize, TSMEM);
                gemm_tc<1><<<grid, block, TSMEM>>>(p); break;
        case 4: cudaFuncSetAttribute(gemm_tc<4>, cudaFuncAttributeMaxDynamicSharedMemorySize, TSMEM);
                gemm_tc<4><<<grid, block, TSMEM>>>(p); break;
        case 5: cudaFuncSetAttribute(gemm_tc<5>, cudaFuncAttributeMaxDynamicSharedMemorySize, TSMEM);
                gemm_tc<5><<<grid, block, TSMEM>>>(p); break;
        case 6: cudaFuncSetAttribute(gemm_tc<6>, cudaFuncAttributeMaxDynamicSharedMemorySize, TSMEM);
                gemm_tc<6><<<grid, block, TSMEM>>>(p); break;
        case 8: cudaFuncSetAttribute(gemm_tc<8>, cudaFuncAttributeMaxDynamicSharedMemorySize, TSMEM);
                gemm_tc<8><<<grid, block, TSMEM>>>(p); break;
    }
}

extern "C" void kernel_launch(void* const* d_in, const int* in_sizes, int n_in,
                              void* d_out, int out_size) {
    const float* x      = (const float*)d_in[0];
    const float* Wq     = (const float*)d_in[1];
    const float* bq     = (const float*)d_in[2];
    const float* Wk     = (const float*)d_in[3];
    const float* bk     = (const float*)d_in[4];
    const float* Wv     = (const float*)d_in[5];
    const float* bv     = (const float*)d_in[6];
    const float* Wo     = (const float*)d_in[7];
    const float* bo     = (const float*)d_in[8];
    const float* gamma1 = (const float*)d_in[9];
    const float* beta1  = (const float*)d_in[10];
    const float* gamma2 = (const float*)d_in[11];
    const float* beta2  = (const float*)d_in[12];
    const float* W1     = (const float*)d_in[13];
    const float* b1     = (const float*)d_in[14];
    const float* W2     = (const float*)d_in[15];
    const float* b2     = (const float*)d_in[16];
    float* out = (float*)d_out;

    void *p_xn1, *p_xn2, *p_xn2f, *p_x2, *p_Wqt, *p_Wkt, *p_Wv15t, *p_Wv0, *p_v0;
    void *p_q, *p_k, *p_v15, *p_v15t, *p_E15, *p_den, *p_num, *p_a15;
    void *p_yc, *p_Wot, *p_W1t, *p_W2t, *p_h1;
    cudaGetSymbolAddress(&p_xn1, g_xn1);   cudaGetSymbolAddress(&p_xn2, g_xn2);
    cudaGetSymbolAddress(&p_xn2f, g_xn2f); cudaGetSymbolAddress(&p_x2, g_x2);
    cudaGetSymbolAddress(&p_Wqt, g_Wqt);   cudaGetSymbolAddress(&p_Wkt, g_Wkt);
    cudaGetSymbolAddress(&p_Wv15t, g_Wv15t); cudaGetSymbolAddress(&p_Wv0, g_Wv0);
    cudaGetSymbolAddress(&p_v0, g_v0);     cudaGetSymbolAddress(&p_q, g_q);
    cudaGetSymbolAddress(&p_k, g_k);       cudaGetSymbolAddress(&p_v15, g_v15);
    cudaGetSymbolAddress(&p_v15t, g_v15t); cudaGetSymbolAddress(&p_E15, g_E15);
    cudaGetSymbolAddress(&p_den, g_den);   cudaGetSymbolAddress(&p_num, g_num);
    cudaGetSymbolAddress(&p_a15, g_a15);   cudaGetSymbolAddress(&p_yc, g_yc);
    cudaGetSymbolAddress(&p_Wot, g_Wot);   cudaGetSymbolAddress(&p_W1t, g_W1t);
    cudaGetSymbolAddress(&p_W2t, g_W2t);   cudaGetSymbolAddress(&p_h1, g_h1);

    __nv_bfloat16* xn1  = (__nv_bfloat16*)p_xn1;
    __nv_bfloat16* xn2  = (__nv_bfloat16*)p_xn2;
    float* xn2f = (float*)p_xn2f;
    float* x2   = (float*)p_x2;
    __nv_bfloat16* Wqt  = (__nv_bfloat16*)p_Wqt;
    __nv_bfloat16* Wkt  = (__nv_bfloat16*)p_Wkt;
    __nv_bfloat16* Wv15t= (__nv_bfloat16*)p_Wv15t;
    float* Wv0  = (float*)p_Wv0;
    float* v0   = (float*)p_v0;
    __nv_bfloat16* q    = (__nv_bfloat16*)p_q;
    __nv_bfloat16* k    = (__nv_bfloat16*)p_k;
    __nv_bfloat16* v15  = (__nv_bfloat16*)p_v15;
    __nv_bfloat16* v15t = (__nv_bfloat16*)p_v15t;
    __nv_bfloat16* E15  = (__nv_bfloat16*)p_E15;
    float* den  = (float*)p_den;
    float* num  = (float*)p_num;
    float* a15  = (float*)p_a15;
    __nv_bfloat16* yc   = (__nv_bfloat16*)p_yc;
    __nv_bfloat16* Wot  = (__nv_bfloat16*)p_Wot;
    __nv_bfloat16* W1t  = (__nv_bfloat16*)p_W1t;
    __nv_bfloat16* W2t  = (__nv_bfloat16*)p_W2t;
    __nv_bfloat16* h1   = (__nv_bfloat16*)p_h1;

    cudaMemsetAsync(den, 0, (size_t)NH * L_SEQ * sizeof(float));
    cudaMemsetAsync(num, 0, (size_t)15 * L_SEQ * sizeof(float));
    cudaMemsetAsync(a15, 0, (size_t)L_SEQ * DA * sizeof(float));
    cudaMemsetAsync(yc,  0, (size_t)L_SEQ * 256 * sizeof(__nv_bfloat16));

    transpose_cvt<<<dim3(DA/32, DE/64, NH), 256>>>(Wq, Wqt, DE, DA, (long)DE*DA, (long)DA*DE);
    transpose_cvt<<<dim3(DA/32, DE/64, NH), 256>>>(Wk, Wkt, DE, DA, (long)DE*DA, (long)DA*DE);
    transpose_cvt<<<dim3(DA/32, DE/64, 1),  256>>>(Wv + (long)15*DE*DA, Wv15t, DE, DA, 0, 0);
    transpose_cvt<<<dim3(DMLP/32, DE/64, 1), 256>>>(W1, W1t, DE, DMLP, 0, 0);
    transpose_cvt<<<dim3(DE/32, DMLP/64, 1), 256>>>(W2, W2t, DMLP, DE, 0, 0);
    wo_prep<<<(256 * DE) / 256, 256>>>(Wo, Wot);
    wv0_prep<<<(15 * DE + 255) / 256, 256>>>(Wv, Wv0);

    ln_kernel<<<L_SEQ, 256>>>(x, gamma1, beta1, xn1, nullptr);

    GP p{};
    const float inv_sqrt_d = 0.08838834764831845f;

    // ---- Q/K projections: tc kernel, head pairs (Z=8, N=256 per pair) ----
    p = GP{xn1, DE, 0, Wqt, DE, (long)256*DE, DE, bq, 0, q, DA, (long)L_SEQ*DA,
           nullptr, nullptr, nullptr, nullptr, nullptr, 0.f};
    launch_tc(8, p, L_SEQ, TBN, 8);
    p = GP{xn1, DE, 0, Wkt, DE, (long)256*DE, DE, bk, 0, k, DA, (long)L_SEQ*DA,
           nullptr, nullptr, nullptr, nullptr, nullptr, 0.f};
    launch_tc(8, p, L_SEQ, TBN, 8);

    // ---- V head 15 (narrow mma.sync) ----
    p = GP{xn1, DE, 0, Wv15t, DE, 0, DE, bv + 15*DA, 0, v15, DA, 0,
           nullptr, nullptr, nullptr, nullptr, nullptr, 0.f};
    launch_narrow(0, p, L_SEQ, DA, 1);

    // ---- v0 matvecs ----
    cudaFuncSetAttribute(v0_kernel, cudaFuncAttributeMaxDynamicSharedMemorySize, 16*DE*2);
    v0_kernel<<<L_SEQ/16, 256, 16*DE*2>>>(xn1, Wv0, bv, v0);

    // ---- heads 0..14: tc fused exp + rowsum + v0-dot (no E store) ----
    p = GP{q, DA, (long)L_SEQ*DA, k, DA, (long)L_SEQ*DA, DA, nullptr, 0,
           nullptr, 0, 0, nullptr, nullptr, den, num, v0, inv_sqrt_d};
    launch_tc(6, p, L_SEQ, L_SEQ, 15);

    // ---- head 15: E15 stored + rowsum (tc) ----
    p = GP{q + (long)15*L_SEQ*DA, DA, 0, k + (long)15*L_SEQ*DA, DA, 0, DA, nullptr, 0,
           E15, L_SEQ, 0, nullptr, nullptr, den + 15*L_SEQ, nullptr, nullptr, inv_sqrt_d};
    launch_tc(1, p, L_SEQ, L_SEQ, 1);

    finalize_cols<<<(15 * L_SEQ + 255) / 256, 256>>>(num, den, yc);

    // ---- A15 = E15 @ v15 (split-K, narrow) ----
    t_v15<<<dim3(DA/32, L_SEQ/32), 256>>>(v15, v15t);
    p = GP{E15, L_SEQ, 256, v15t, L_SEQ, 256, 256, nullptr, 0,
           a15, DA, 0, nullptr, nullptr, nullptr, nullptr, nullptr, 0.f};
    launch_narrow(7, p, L_SEQ, DA, 8);
    finalize15<<<(L_SEQ * DA) / 256, 256>>>(a15, den + 15*L_SEQ, yc);

    // ---- x2 = 2x + yc @ Wo' + bo (narrow) ----
    p = GP{yc, 256, 0, Wot, 256, 0, 256, bo, 0, x2, DE, 0,
           x, nullptr, nullptr, nullptr, nullptr, 0.f};
    launch_narrow(3, p, L_SEQ, DE, 1);

    ln_kernel<<<L_SEQ, 256>>>(x2, gamma2, beta2, xn2, xn2f);

    // ---- h1 = gelu(xn2 @ W1 + b1) (tc) ----
    p = GP{xn2, DE, 0, W1t, DE, 0, DE, b1, 0, h1, DMLP, 0,
           nullptr, nullptr, nullptr, nullptr, nullptr, 0.f};
    launch_tc(4, p, L_SEQ, DMLP, 1);

    // ---- out = h1 @ W2 + b2 + x2 + xn2 (tc) ----
    p = GP{h1, DMLP, 0, W2t, DMLP, 0, DMLP, b2, 0, out, DE, 0,
           x2, xn2f, nullptr, nullptr, nullptr, 0.f};
    launch_tc(5, p, L_SEQ, DE, 1);
}